// round 1
// baseline (speedup 1.0000x reference)
#include <cuda_runtime.h>

#define BATCH 4096
#define D 256
#define N2 8192   // 2*BATCH

// ---------------- device scratch (no runtime allocation allowed) ----------------
__device__ double g_sum_sq;
__device__ double g_colsum[D];
__device__ float  g_sq[N2];
__device__ float  g_g0;
__device__ double g_disc;

// ---------------- init: zero accumulators (graph replays re-run this) ----------------
__global__ void init_kernel() {
    int t = threadIdx.x;
    if (t == 0) { g_sum_sq = 0.0; g_disc = 0.0; }
    if (t < D) g_colsum[t] = 0.0;
}

// ---------------- per-row squared norms; one warp per row ----------------
__global__ void rowsq_kernel(const float* __restrict__ S, const float* __restrict__ T) {
    int warp = threadIdx.x >> 5, lane = threadIdx.x & 31;
    int row = blockIdx.x * 8 + warp;
    const float* F = (row < BATCH) ? (S + (size_t)row * D) : (T + (size_t)(row - BATCH) * D);
    float4 a = ((const float4*)F)[lane];
    float4 b = ((const float4*)F)[lane + 32];
    float s = a.x*a.x + a.y*a.y + a.z*a.z + a.w*a.w
            + b.x*b.x + b.y*b.y + b.z*b.z + b.w*b.w;
    #pragma unroll
    for (int off = 16; off > 0; off >>= 1)
        s += __shfl_down_sync(0xffffffffu, s, off);
    if (lane == 0) {
        g_sq[row] = s;
        atomicAdd(&g_sum_sq, (double)s);
    }
}

// ---------------- column sums (coalesced: thread = column) ----------------
__global__ void colsum_kernel(const float* __restrict__ S, const float* __restrict__ T) {
    int c = threadIdx.x;                 // 0..255 = column
    int r0 = blockIdx.x * 128;           // rows of concat space
    float p = 0.f;
    #pragma unroll 4
    for (int r = r0; r < r0 + 128; ++r) {
        const float* F = (r < BATCH) ? (S + (size_t)r * D) : (T + (size_t)(r - BATCH) * D);
        p += F[c];
    }
    atomicAdd(&g_colsum[c], (double)p);
}

// ---------------- bandwidth: sum_dist = 2n*sum_sq - 2*||colsum||^2 ----------------
__global__ void bw_kernel() {
    __shared__ double red[D];
    int t = threadIdx.x;
    double v = g_colsum[t];
    red[t] = v * v;
    __syncthreads();
    for (int s = 128; s > 0; s >>= 1) {
        if (t < s) red[t] += red[t + s];
        __syncthreads();
    }
    if (t == 0) {
        double sum_dist = 2.0 * (double)N2 * g_sum_sq - 2.0 * red[0];
        double bandwidth = ((double)N2 * (double)N2 - (double)N2) / sum_dist;
        g_g0 = (float)(bandwidth / 4.0);   // / 2^(NUM_KERNELS//2)
    }
}

// sum of 5 gaussians via repeated squaring: e + e^2 + e^4 + e^8 + e^16
__device__ __forceinline__ float kernsum5(float d, float ng0l2e) {
    float e  = exp2f(d * ng0l2e);
    float e2 = e * e, e4 = e2 * e2, e8 = e4 * e4, e16 = e8 * e8;
    return e + e2 + e4 + e8 + e16;
}

// ---------------- main: fused 3-block pairwise kernel + reduction ----------------
// 64x64 output tile per block, 256 threads (16x16), 4x4 micro-tile, 3 accumulators.
__global__ __launch_bounds__(256) void mmd_main(const float* __restrict__ S,
                                                const float* __restrict__ T) {
    __shared__ float smSi[32][65], smTi[32][65], smSj[32][65], smTj[32][65];
    __shared__ float sqSi[64], sqTi[64], sqSj[64], sqTj[64];
    __shared__ float red[256];

    int tid = threadIdx.x;
    int tx = tid & 15, ty = tid >> 4;
    int i0 = blockIdx.y * 64, j0 = blockIdx.x * 64;

    // stage squared norms for this tile
    if (tid < 64)        sqSi[tid]       = g_sq[i0 + tid];
    else if (tid < 128)  sqTi[tid - 64]  = g_sq[BATCH + i0 + (tid - 64)];
    else if (tid < 192)  sqSj[tid - 128] = g_sq[j0 + (tid - 128)];
    else                 sqTj[tid - 192] = g_sq[BATCH + j0 + (tid - 192)];
    float g0 = g_g0;

    float accss[4][4] = {}, acctt[4][4] = {}, accst[4][4] = {};

    int kf = tid & 7;    // float4 index within 32-wide k chunk
    int r0 = tid >> 3;   // 0..31

    for (int k0 = 0; k0 < D; k0 += 32) {
        __syncthreads();
        #pragma unroll
        for (int h = 0; h < 2; ++h) {
            int row = r0 + h * 32;
            float4 vsi = *(const float4*)(S + (size_t)(i0 + row) * D + k0 + kf * 4);
            float4 vti = *(const float4*)(T + (size_t)(i0 + row) * D + k0 + kf * 4);
            float4 vsj = *(const float4*)(S + (size_t)(j0 + row) * D + k0 + kf * 4);
            float4 vtj = *(const float4*)(T + (size_t)(j0 + row) * D + k0 + kf * 4);
            smSi[kf*4+0][row] = vsi.x; smSi[kf*4+1][row] = vsi.y;
            smSi[kf*4+2][row] = vsi.z; smSi[kf*4+3][row] = vsi.w;
            smTi[kf*4+0][row] = vti.x; smTi[kf*4+1][row] = vti.y;
            smTi[kf*4+2][row] = vti.z; smTi[kf*4+3][row] = vti.w;
            smSj[kf*4+0][row] = vsj.x; smSj[kf*4+1][row] = vsj.y;
            smSj[kf*4+2][row] = vsj.z; smSj[kf*4+3][row] = vsj.w;
            smTj[kf*4+0][row] = vtj.x; smTj[kf*4+1][row] = vtj.y;
            smTj[kf*4+2][row] = vtj.z; smTj[kf*4+3][row] = vtj.w;
        }
        __syncthreads();
        #pragma unroll
        for (int k = 0; k < 32; ++k) {
            float as[4], at[4], bs[4], bt[4];
            #pragma unroll
            for (int m = 0; m < 4; ++m) { as[m] = smSi[k][ty*4+m]; at[m] = smTi[k][ty*4+m]; }
            #pragma unroll
            for (int n = 0; n < 4; ++n) { bs[n] = smSj[k][tx*4+n]; bt[n] = smTj[k][tx*4+n]; }
            #pragma unroll
            for (int m = 0; m < 4; ++m)
                #pragma unroll
                for (int n = 0; n < 4; ++n) {
                    accss[m][n] += as[m] * bs[n];
                    acctt[m][n] += at[m] * bt[n];
                    accst[m][n] += as[m] * bt[n];
                }
        }
    }
    __syncthreads();

    float ng = -g0 * 1.44269504088896340736f;  // -g0 * log2(e)
    float c = 0.f;
    #pragma unroll
    for (int m = 0; m < 4; ++m) {
        float si = sqSi[ty*4+m], ti = sqTi[ty*4+m];
        #pragma unroll
        for (int n = 0; n < 4; ++n) {
            float sj = sqSj[tx*4+n], tj = sqTj[tx*4+n];
            float dss = fmaxf(si + sj - 2.f * accss[m][n], 0.f);
            float dtt = fmaxf(ti + tj - 2.f * acctt[m][n], 0.f);
            float dst = fmaxf(si + tj - 2.f * accst[m][n], 0.f);
            c += kernsum5(dss, ng) + kernsum5(dtt, ng) - 2.f * kernsum5(dst, ng);
        }
    }

    red[tid] = c;
    __syncthreads();
    for (int s = 128; s > 0; s >>= 1) {
        if (tid < s) red[tid] += red[tid + s];
        __syncthreads();
    }
    if (tid == 0) atomicAdd(&g_disc, (double)red[0]);
}

// ---------------- finalize: disc = sum / 5 / (B*B) ----------------
__global__ void finish_kernel(float* out) {
    out[0] = (float)(g_disc / (5.0 * (double)BATCH * (double)BATCH));
}

extern "C" void kernel_launch(void* const* d_in, const int* in_sizes, int n_in,
                              void* d_out, int out_size) {
    const float* S = (const float*)d_in[0];
    const float* T = (const float*)d_in[1];
    init_kernel<<<1, 256>>>();
    rowsq_kernel<<<N2 / 8, 256>>>(S, T);
    colsum_kernel<<<N2 / 128, 256>>>(S, T);
    bw_kernel<<<1, D>>>();
    mmd_main<<<dim3(BATCH / 64, BATCH / 64), 256>>>(S, T);
    finish_kernel<<<1, 1>>>((float*)d_out);
}

// round 6
// speedup vs baseline: 9.2480x; 9.2480x over previous
#include <cuda_runtime.h>
#include <cuda_fp16.h>
#include <cstdint>

#define BATCH 4096
#define D 256
#define N2 8192
#define NTILE 64                       // 8192 / 128
#define NBLK (NTILE * (NTILE + 1) / 2) // 2080

// ---------------- device scratch ----------------
__device__ double g_sum_sq;
__device__ double g_colsum[D];
__device__ float  g_sq[N2];
__device__ float  g_g0;
__device__ double g_disc;
__device__ __align__(16) __half g_half[(size_t)N2 * D];

__device__ __forceinline__ uint32_t smem_u32(const void* p) {
    uint32_t a;
    asm("{ .reg .u64 t; cvta.to.shared.u64 t, %1; cvt.u32.u64 %0, t; }" : "=r"(a) : "l"(p));
    return a;
}

// ---------------- prologue ----------------
__global__ void init_kernel() {
    int t = threadIdx.x;
    if (t == 0) { g_sum_sq = 0.0; g_disc = 0.0; }
    if (t < D) g_colsum[t] = 0.0;
}

// row squared-norms (fp32 exact) + fp32 -> fp16 convert, fused
__global__ void rowsq_convert(const float* __restrict__ S, const float* __restrict__ T) {
    int warp = threadIdx.x >> 5, lane = threadIdx.x & 31;
    int row = blockIdx.x * 8 + warp;
    const float* F = (row < BATCH) ? (S + (size_t)row * D) : (T + (size_t)(row - BATCH) * D);
    float4 a = ((const float4*)F)[lane];
    float4 b = ((const float4*)F)[lane + 32];
    float s = a.x*a.x + a.y*a.y + a.z*a.z + a.w*a.w
            + b.x*b.x + b.y*b.y + b.z*b.z + b.w*b.w;
    __half2* H = (__half2*)(g_half + (size_t)row * D);
    H[lane * 2 + 0]      = __floats2half2_rn(a.x, a.y);
    H[lane * 2 + 1]      = __floats2half2_rn(a.z, a.w);
    H[64 + lane * 2 + 0] = __floats2half2_rn(b.x, b.y);
    H[64 + lane * 2 + 1] = __floats2half2_rn(b.z, b.w);
    #pragma unroll
    for (int off = 16; off > 0; off >>= 1) s += __shfl_down_sync(0xffffffffu, s, off);
    if (lane == 0) { g_sq[row] = s; atomicAdd(&g_sum_sq, (double)s); }
}

__global__ void colsum_kernel(const float* __restrict__ S, const float* __restrict__ T) {
    int c = threadIdx.x;
    int r0 = blockIdx.x * 128;
    float p = 0.f;
    #pragma unroll 4
    for (int r = r0; r < r0 + 128; ++r) {
        const float* F = (r < BATCH) ? (S + (size_t)r * D) : (T + (size_t)(r - BATCH) * D);
        p += F[c];
    }
    atomicAdd(&g_colsum[c], (double)p);
}

__global__ void bw_kernel() {
    __shared__ double red[D];
    int t = threadIdx.x;
    double v = g_colsum[t];
    red[t] = v * v;
    __syncthreads();
    for (int s = 128; s > 0; s >>= 1) { if (t < s) red[t] += red[t + s]; __syncthreads(); }
    if (t == 0) {
        double sum_dist = 2.0 * (double)N2 * g_sum_sq - 2.0 * red[0];
        double bandwidth = ((double)N2 * (double)N2 - (double)N2) / sum_dist;
        g_g0 = (float)(bandwidth / 4.0);   // / 2^(NUM_KERNELS//2)
    }
}

// 2^x (FMA-pipe poly, no MUFU) then e + e^2 + e^4 + e^8 + e^16
__device__ __forceinline__ float kern5x(float x) {
    float t = x + 12582912.f;
    int   ni = __float_as_int(t) - 0x4B400000;
    float n = t - 12582912.f;
    float f = x - n;
    float p = 1.540353e-4f;
    p = fmaf(p, f, 1.3333558e-3f);
    p = fmaf(p, f, 9.6181291e-3f);
    p = fmaf(p, f, 5.55041087e-2f);
    p = fmaf(p, f, 2.402265069e-1f);
    p = fmaf(p, f, 6.931471806e-1f);
    p = fmaf(p, f, 1.0f);
    float e = __int_as_float((127 + ni) << 23) * p;
    float e2 = e * e, e4 = e2 * e2, e8 = e4 * e4;
    return e + e2 + e4 + e8 + e8 * e8;
}

// ---------------- main: HMMA register-tile kernel ----------------
// 128x128 tile, 8 warps in 4(m) x 2(n), warp tile 32x64, mma m16n8k16 fp16->f32.
__global__ void __launch_bounds__(256, 2) mmd_mma() {
    __shared__ __align__(1024) uint8_t smA[128 * 128];   // 128 rows x 64 halves (128B/row)
    __shared__ __align__(1024) uint8_t smB[128 * 128];
    __shared__ float sqj[128];
    __shared__ float red[8];

    const int tid = threadIdx.x;
    const int wid = tid >> 5, lane = tid & 31;
    const int wm = wid & 3, wn = wid >> 2;
    const int g = lane >> 2, j4 = lane & 3;

    // triangular tile index
    int x = blockIdx.x;
    int bi = (int)((sqrtf(8.f * x + 1.f) - 1.f) * 0.5f);
    while ((bi + 1) * (bi + 2) / 2 <= x) bi++;
    while (bi * (bi + 1) / 2 > x) bi--;
    int bj = x - bi * (bi + 1) / 2;
    const int i0 = bi * 128, j0 = bj * 128;

    if (tid < 128) sqj[tid] = g_sq[j0 + tid];

    const uint32_t sbA = smem_u32(smA), sbB = smem_u32(smB);

    // ldmatrix swizzled base addresses. k-step delta (ks*32, bits 5-6) never
    // overlaps the unswizzled column bits (0 or 16), so addr(ks) = base ^ (ks*32).
    uint32_t abase[2], bbase[4];
    {
        int rA = wm * 32 + (lane & 15);
        int ca = (lane >> 4) * 16;
        #pragma unroll
        for (int mi = 0; mi < 2; ++mi) {
            uint32_t base = (uint32_t)((rA + mi * 16) * 128 + ca);
            abase[mi] = sbA + (base ^ ((base >> 3) & 0x70));
        }
        int rB = wn * 64 + (lane & 7) + ((lane >= 16) ? 8 : 0);
        int cb = (((lane >> 3) & 1) ? 16 : 0);
        #pragma unroll
        for (int nj = 0; nj < 4; ++nj) {
            uint32_t base = (uint32_t)((rB + nj * 16) * 128 + cb);
            bbase[nj] = sbB + (base ^ ((base >> 3) & 0x70));
        }
    }

    float acc[2][8][4];
    #pragma unroll
    for (int mi = 0; mi < 2; ++mi)
        #pragma unroll
        for (int ni = 0; ni < 8; ++ni)
            #pragma unroll
            for (int q = 0; q < 4; ++q) acc[mi][ni][q] = 0.f;

    for (int c = 0; c < 4; ++c) {
        const int kc = c * 64;
        if (c) __syncthreads();
        #pragma unroll
        for (int r = 0; r < 4; ++r) {
            int idx = tid + r * 256;
            int row = idx >> 3, f4 = idx & 7;
            uint4 va = *(const uint4*)(g_half + (size_t)(i0 + row) * D + kc + f4 * 8);
            uint4 vb = *(const uint4*)(g_half + (size_t)(j0 + row) * D + kc + f4 * 8);
            uint32_t bo = (uint32_t)(row * 128 + f4 * 16);
            bo ^= (bo >> 3) & 0x70;
            *(uint4*)(smA + bo) = va;
            *(uint4*)(smB + bo) = vb;
        }
        __syncthreads();
        #pragma unroll
        for (int ks = 0; ks < 4; ++ks) {
            uint32_t a[2][4], b[4][4];
            #pragma unroll
            for (int mi = 0; mi < 2; ++mi)
                asm volatile("ldmatrix.sync.aligned.m8n8.x4.shared.b16 {%0,%1,%2,%3}, [%4];"
                    : "=r"(a[mi][0]), "=r"(a[mi][1]), "=r"(a[mi][2]), "=r"(a[mi][3])
                    : "r"(abase[mi] ^ (ks * 32)));
            #pragma unroll
            for (int nj = 0; nj < 4; ++nj)
                asm volatile("ldmatrix.sync.aligned.m8n8.x4.shared.b16 {%0,%1,%2,%3}, [%4];"
                    : "=r"(b[nj][0]), "=r"(b[nj][1]), "=r"(b[nj][2]), "=r"(b[nj][3])
                    : "r"(bbase[nj] ^ (ks * 32)));
            #pragma unroll
            for (int mi = 0; mi < 2; ++mi)
                #pragma unroll
                for (int ni = 0; ni < 8; ++ni) {
                    uint32_t b0 = b[ni >> 1][(ni & 1) * 2];
                    uint32_t b1 = b[ni >> 1][(ni & 1) * 2 + 1];
                    asm volatile(
                        "mma.sync.aligned.m16n8k16.row.col.f32.f16.f16.f32 "
                        "{%0,%1,%2,%3}, {%4,%5,%6,%7}, {%8,%9}, {%0,%1,%2,%3};"
                        : "+f"(acc[mi][ni][0]), "+f"(acc[mi][ni][1]),
                          "+f"(acc[mi][ni][2]), "+f"(acc[mi][ni][3])
                        : "r"(a[mi][0]), "r"(a[mi][1]), "r"(a[mi][2]), "r"(a[mi][3]),
                          "r"(b0), "r"(b1));
                }
        }
    }

    // ---------------- epilogue ----------------
    const float ng = -g_g0 * 1.44269504088896340736f;   // -g0 * log2(e)
    float sqi[2][2];
    #pragma unroll
    for (int mi = 0; mi < 2; ++mi) {
        sqi[mi][0] = g_sq[i0 + wm * 32 + mi * 16 + g];
        sqi[mi][1] = g_sq[i0 + wm * 32 + mi * 16 + g + 8];
    }
    float accsum = 0.f;
    #pragma unroll
    for (int mi = 0; mi < 2; ++mi)
        #pragma unroll
        for (int ni = 0; ni < 8; ++ni) {
            int cb = wn * 64 + ni * 8 + 2 * j4;
            float sj0 = sqj[cb], sj1 = sqj[cb + 1];
            float d0 = fmaxf(sqi[mi][0] + sj0 - 2.f * acc[mi][ni][0], 0.f);
            float d1 = fmaxf(sqi[mi][0] + sj1 - 2.f * acc[mi][ni][1], 0.f);
            float d2 = fmaxf(sqi[mi][1] + sj0 - 2.f * acc[mi][ni][2], 0.f);
            float d3 = fmaxf(sqi[mi][1] + sj1 - 2.f * acc[mi][ni][3], 0.f);
            accsum += kern5x(d0 * ng) + kern5x(d1 * ng)
                    + kern5x(d2 * ng) + kern5x(d3 * ng);
        }

    float w = (((i0 < BATCH) == (j0 < BATCH)) ? 1.f : -1.f) * ((bi == bj) ? 1.f : 2.f);
    accsum *= w;
    #pragma unroll
    for (int off = 16; off > 0; off >>= 1)
        accsum += __shfl_down_sync(0xffffffffu, accsum, off);
    if (lane == 0) red[wid] = accsum;
    __syncthreads();
    if (tid == 0) {
        double s = 0.0;
        #pragma unroll
        for (int i = 0; i < 8; ++i) s += (double)red[i];
        atomicAdd(&g_disc, s);
    }
}

__global__ void finish_kernel(float* out) {
    out[0] = (float)(g_disc / (5.0 * (double)BATCH * (double)BATCH));
}

extern "C" void kernel_launch(void* const* d_in, const int* in_sizes, int n_in,
                              void* d_out, int out_size) {
    const float* S = (const float*)d_in[0];
    const float* T = (const float*)d_in[1];
    init_kernel<<<1, 256>>>();
    rowsq_convert<<<N2 / 8, 256>>>(S, T);
    colsum_kernel<<<N2 / 128, 256>>>(S, T);
    bw_kernel<<<1, D>>>();
    mmd_mma<<<NBLK, 256>>>();
    finish_kernel<<<1, 1>>>((float*)d_out);
}

// round 7
// speedup vs baseline: 11.1731x; 1.2082x over previous
#include <cuda_runtime.h>
#include <cuda_fp16.h>
#include <cstdint>

#define BATCH 4096
#define D 256
#define N2 8192
#define NTILE 64                       // 8192 / 128
#define NBLK (NTILE * (NTILE + 1) / 2) // 2080
#define GRID_MAIN 296                  // 2 CTAs/SM * 148 SMs

// ---------------- device scratch ----------------
__device__ double g_colsum[D];
__device__ float  g_sq[N2];
__device__ float  g_g0;
__device__ double g_disc;
__device__ __align__(16) __half g_half[(size_t)N2 * D];

__device__ __forceinline__ uint32_t smem_u32(const void* p) {
    uint32_t a;
    asm("{ .reg .u64 t; cvta.to.shared.u64 t, %1; cvt.u32.u64 %0, t; }" : "=r"(a) : "l"(p));
    return a;
}
#define CP_ASYNC16(dst, src) asm volatile("cp.async.ca.shared.global [%0], [%1], 16;" :: "r"(dst), "l"(src))
#define CP_COMMIT()          asm volatile("cp.async.commit_group;" ::: "memory")
#define CP_WAIT(n)           asm volatile("cp.async.wait_group %0;" :: "n"(n) : "memory")

// ---------------- init ----------------
__global__ void init_kernel() {
    int t = threadIdx.x;
    if (t == 0) g_disc = 0.0;
    if (t < D) g_colsum[t] = 0.0;
}

// ---------------- fused prologue: rowsq + fp16 convert + colsum, one pass ----------------
// 128 blocks x 256 threads; block handles 64 rows; warp-per-row, 8 rows/warp.
__global__ void prologue_kernel(const float* __restrict__ S, const float* __restrict__ T) {
    __shared__ float cs[256];
    const int tid = threadIdx.x, w = tid >> 5, lane = tid & 31;
    cs[tid] = 0.f;
    __syncthreads();
    float cp[8] = {0.f, 0.f, 0.f, 0.f, 0.f, 0.f, 0.f, 0.f};
    const int base = blockIdx.x * 64;
    #pragma unroll
    for (int r = 0; r < 8; ++r) {
        int row = base + r * 8 + w;
        const float* F = (row < BATCH) ? (S + (size_t)row * D) : (T + (size_t)(row - BATCH) * D);
        float4 a = ((const float4*)F)[lane];
        float4 b = ((const float4*)F)[lane + 32];
        cp[0] += a.x; cp[1] += a.y; cp[2] += a.z; cp[3] += a.w;
        cp[4] += b.x; cp[5] += b.y; cp[6] += b.z; cp[7] += b.w;
        float s = a.x*a.x + a.y*a.y + a.z*a.z + a.w*a.w
                + b.x*b.x + b.y*b.y + b.z*b.z + b.w*b.w;
        __half2* H = (__half2*)(g_half + (size_t)row * D);
        H[lane * 2 + 0]      = __floats2half2_rn(a.x, a.y);
        H[lane * 2 + 1]      = __floats2half2_rn(a.z, a.w);
        H[64 + lane * 2 + 0] = __floats2half2_rn(b.x, b.y);
        H[64 + lane * 2 + 1] = __floats2half2_rn(b.z, b.w);
        #pragma unroll
        for (int off = 16; off > 0; off >>= 1) s += __shfl_down_sync(0xffffffffu, s, off);
        if (lane == 0) g_sq[row] = s;
    }
    #pragma unroll
    for (int q = 0; q < 4; ++q) atomicAdd(&cs[4 * lane + q], cp[q]);
    #pragma unroll
    for (int q = 0; q < 4; ++q) atomicAdd(&cs[128 + 4 * lane + q], cp[4 + q]);
    __syncthreads();
    atomicAdd(&g_colsum[tid], (double)cs[tid]);
}

// ---------------- bandwidth (also reduces sum_sq from g_sq) ----------------
__global__ void bw_kernel() {
    __shared__ double rs[256], rc[256];
    int t = threadIdx.x;
    float s = 0.f;
    for (int i = t; i < N2; i += 256) s += g_sq[i];
    rs[t] = (double)s;
    double v = g_colsum[t];
    rc[t] = v * v;
    __syncthreads();
    for (int k = 128; k > 0; k >>= 1) {
        if (t < k) { rs[t] += rs[t + k]; rc[t] += rc[t + k]; }
        __syncthreads();
    }
    if (t == 0) {
        double sum_dist = 2.0 * (double)N2 * rs[0] - 2.0 * rc[0];
        double bandwidth = ((double)N2 * (double)N2 - (double)N2) / sum_dist;
        g_g0 = (float)(bandwidth / 4.0);   // / 2^(NUM_KERNELS//2)
    }
}

// 2^x (FMA-pipe poly, no MUFU) then e + e^2 + e^4 + e^8 + e^16
__device__ __forceinline__ float kern5x(float x) {
    float t = x + 12582912.f;
    int   ni = __float_as_int(t) - 0x4B400000;
    float n = t - 12582912.f;
    float f = x - n;
    float p = 1.540353e-4f;
    p = fmaf(p, f, 1.3333558e-3f);
    p = fmaf(p, f, 9.6181291e-3f);
    p = fmaf(p, f, 5.55041087e-2f);
    p = fmaf(p, f, 2.402265069e-1f);
    p = fmaf(p, f, 6.931471806e-1f);
    p = fmaf(p, f, 1.0f);
    float e = __int_as_float((127 + ni) << 23) * p;
    float e2 = e * e, e4 = e2 * e2, e8 = e4 * e4;
    return e + e2 + e4 + e8 + e8 * e8;
}

// ---------------- main: persistent HMMA kernel, cp.async double-buffered ----------------
// dynamic smem: [0,32K) A bufs, [32K,64K) B bufs, [64K,+512) sqj, then red[8]
#define SM_A     0
#define SM_B     32768
#define SM_SQJ   65536
#define SM_RED   66048
#define SMEM_TOTAL 66112

__global__ void __launch_bounds__(256, 2) mmd_mma() {
    extern __shared__ __align__(1024) uint8_t dsm[];
    float* sqj = (float*)(dsm + SM_SQJ);
    float* red = (float*)(dsm + SM_RED);

    const int tid = threadIdx.x;
    const int wid = tid >> 5, lane = tid & 31;
    const int wm = wid & 3, wn = wid >> 2;
    const int g = lane >> 2, j4 = lane & 3;
    const uint32_t sb = smem_u32(dsm);

    // ldmatrix swizzled offsets within a 16KB buffer (k-step XORs bits 5-6)
    uint32_t aoff[2], boff[4];
    {
        int rA = wm * 32 + (lane & 15);
        int ca = (lane >> 4) * 16;
        #pragma unroll
        for (int mi = 0; mi < 2; ++mi) {
            uint32_t b0 = (uint32_t)((rA + mi * 16) * 128 + ca);
            aoff[mi] = b0 ^ ((b0 >> 3) & 0x70);
        }
        int rB = wn * 64 + (lane & 7) + ((lane >= 16) ? 8 : 0);
        int cb = (((lane >> 3) & 1) ? 16 : 0);
        #pragma unroll
        for (int nj = 0; nj < 4; ++nj) {
            uint32_t b0 = (uint32_t)((rB + nj * 16) * 128 + cb);
            boff[nj] = b0 ^ ((b0 >> 3) & 0x70);
        }
    }
    // cp.async store offset for this thread (row = tid>>3, f4 = tid&7), 4 rounds of +32 rows
    uint32_t stoff[4];
    #pragma unroll
    for (int r = 0; r < 4; ++r) {
        uint32_t b0 = (uint32_t)(((tid >> 3) + r * 32) * 128 + (tid & 7) * 16);
        stoff[r] = b0 ^ ((b0 >> 3) & 0x70);
    }
    const int ldrow = tid >> 3, ldf4 = tid & 7;

    const float ng = -g_g0 * 1.44269504088896340736f;
    double dacc = 0.0;

    for (int x = blockIdx.x; x < NBLK; x += GRID_MAIN) {
        // triangular tile index
        int bi = (int)((sqrtf(8.f * x + 1.f) - 1.f) * 0.5f);
        while ((bi + 1) * (bi + 2) / 2 <= x) bi++;
        while (bi * (bi + 1) / 2 > x) bi--;
        int bj = x - bi * (bi + 1) / 2;
        const int i0 = bi * 128, j0 = bj * 128;

        if (tid < 128) sqj[tid] = g_sq[j0 + tid];

        // prefetch chunk 0
        {
            const __half* pa = g_half + (size_t)(i0 + ldrow) * D + ldf4 * 8;
            const __half* pb = g_half + (size_t)(j0 + ldrow) * D + ldf4 * 8;
            #pragma unroll
            for (int r = 0; r < 4; ++r) {
                CP_ASYNC16(sb + SM_A + stoff[r], pa + (size_t)r * 32 * D);
                CP_ASYNC16(sb + SM_B + stoff[r], pb + (size_t)r * 32 * D);
            }
            CP_COMMIT();
        }

        float acc[2][8][4];
        #pragma unroll
        for (int mi = 0; mi < 2; ++mi)
            #pragma unroll
            for (int ni = 0; ni < 8; ++ni)
                #pragma unroll
                for (int q = 0; q < 4; ++q) acc[mi][ni][q] = 0.f;

        #pragma unroll
        for (int c = 0; c < 4; ++c) {
            const uint32_t bufA = sb + SM_A + (c & 1) * 16384;
            const uint32_t bufB = sb + SM_B + (c & 1) * 16384;
            if (c < 3) {   // prefetch next chunk into other buffer
                const int kc = (c + 1) * 64;
                const uint32_t nbA = sb + SM_A + ((c + 1) & 1) * 16384;
                const uint32_t nbB = sb + SM_B + ((c + 1) & 1) * 16384;
                const __half* pa = g_half + (size_t)(i0 + ldrow) * D + kc + ldf4 * 8;
                const __half* pb = g_half + (size_t)(j0 + ldrow) * D + kc + ldf4 * 8;
                #pragma unroll
                for (int r = 0; r < 4; ++r) {
                    CP_ASYNC16(nbA + stoff[r], pa + (size_t)r * 32 * D);
                    CP_ASYNC16(nbB + stoff[r], pb + (size_t)r * 32 * D);
                }
                CP_COMMIT();
                CP_WAIT(1);
            } else {
                CP_WAIT(0);
            }
            __syncthreads();
            #pragma unroll
            for (int ks = 0; ks < 4; ++ks) {
                uint32_t a[2][4], b[4][4];
                #pragma unroll
                for (int mi = 0; mi < 2; ++mi)
                    asm volatile("ldmatrix.sync.aligned.m8n8.x4.shared.b16 {%0,%1,%2,%3}, [%4];"
                        : "=r"(a[mi][0]), "=r"(a[mi][1]), "=r"(a[mi][2]), "=r"(a[mi][3])
                        : "r"(bufA + (aoff[mi] ^ (ks * 32))));
                #pragma unroll
                for (int nj = 0; nj < 4; ++nj)
                    asm volatile("ldmatrix.sync.aligned.m8n8.x4.shared.b16 {%0,%1,%2,%3}, [%4];"
                        : "=r"(b[nj][0]), "=r"(b[nj][1]), "=r"(b[nj][2]), "=r"(b[nj][3])
                        : "r"(bufB + (boff[nj] ^ (ks * 32))));
                #pragma unroll
                for (int mi = 0; mi < 2; ++mi)
                    #pragma unroll
                    for (int ni = 0; ni < 8; ++ni) {
                        uint32_t b0 = b[ni >> 1][(ni & 1) * 2];
                        uint32_t b1 = b[ni >> 1][(ni & 1) * 2 + 1];
                        asm volatile(
                            "mma.sync.aligned.m16n8k16.row.col.f32.f16.f16.f32 "
                            "{%0,%1,%2,%3}, {%4,%5,%6,%7}, {%8,%9}, {%0,%1,%2,%3};"
                            : "+f"(acc[mi][ni][0]), "+f"(acc[mi][ni][1]),
                              "+f"(acc[mi][ni][2]), "+f"(acc[mi][ni][3])
                            : "r"(a[mi][0]), "r"(a[mi][1]), "r"(a[mi][2]), "r"(a[mi][3]),
                              "r"(b0), "r"(b1));
                    }
            }
            __syncthreads();
        }

        // ---------------- epilogue ----------------
        float sqi[2][2];
        #pragma unroll
        for (int mi = 0; mi < 2; ++mi) {
            sqi[mi][0] = g_sq[i0 + wm * 32 + mi * 16 + g];
            sqi[mi][1] = g_sq[i0 + wm * 32 + mi * 16 + g + 8];
        }
        float accsum = 0.f;
        #pragma unroll
        for (int mi = 0; mi < 2; ++mi)
            #pragma unroll
            for (int ni = 0; ni < 8; ++ni) {
                int cb = wn * 64 + ni * 8 + 2 * j4;
                float sj0 = sqj[cb], sj1 = sqj[cb + 1];
                float d0 = fmaxf(sqi[mi][0] + sj0 - 2.f * acc[mi][ni][0], 0.f);
                float d1 = fmaxf(sqi[mi][0] + sj1 - 2.f * acc[mi][ni][1], 0.f);
                float d2 = fmaxf(sqi[mi][1] + sj0 - 2.f * acc[mi][ni][2], 0.f);
                float d3 = fmaxf(sqi[mi][1] + sj1 - 2.f * acc[mi][ni][3], 0.f);
                accsum += kern5x(d0 * ng) + kern5x(d1 * ng)
                        + kern5x(d2 * ng) + kern5x(d3 * ng);
            }
        float w = (((i0 < BATCH) == (j0 < BATCH)) ? 1.f : -1.f) * ((bi == bj) ? 1.f : 2.f);
        accsum *= w;
        #pragma unroll
        for (int off = 16; off > 0; off >>= 1)
            accsum += __shfl_down_sync(0xffffffffu, accsum, off);
        if (lane == 0) red[wid] = accsum;
        __syncthreads();
        if (tid == 0) {
            float s = 0.f;
            #pragma unroll
            for (int i = 0; i < 8; ++i) s += red[i];
            dacc += (double)s;
        }
        __syncthreads();   // red/sqj safe to reuse next tile
    }
    if (tid == 0) atomicAdd(&g_disc, dacc);
}

__global__ void finish_kernel(float* out) {
    out[0] = (float)(g_disc / (5.0 * (double)BATCH * (double)BATCH));
}

extern "C" void kernel_launch(void* const* d_in, const int* in_sizes, int n_in,
                              void* d_out, int out_size) {
    const float* S = (const float*)d_in[0];
    const float* T = (const float*)d_in[1];
    cudaFuncSetAttribute(mmd_mma, cudaFuncAttributeMaxDynamicSharedMemorySize, SMEM_TOTAL);
    init_kernel<<<1, 256>>>();
    prologue_kernel<<<128, 256>>>(S, T);
    bw_kernel<<<1, 256>>>();
    mmd_mma<<<GRID_MAIN, 256, SMEM_TOTAL>>>();
    finish_kernel<<<1, 1>>>((float*)d_out);
}